// round 6
// baseline (speedup 1.0000x reference)
#include <cuda_runtime.h>

// Problem constants
#define B_   128
#define T_   256
#define I_   256
#define H_   1024
#define C_   10
#define LRC  0.001f

#define NCTA 128
#define NTHR 256

// ---------------- device scratch (no allocs allowed) ----------------
__device__ float g_h[2][B_ * H_];   // double-buffered hidden state
__device__ float g_z[B_ * H_];      // pre-activation Z per step
__device__ unsigned g_cnt = 0;
__device__ unsigned g_sense = 0;

// Sense-reversing grid barrier. Safe: grid=128 CTAs <= 148 SMs, all co-resident.
// State self-resets (cnt back to 0, sense toggles) so repeated graph replays work.
__device__ __forceinline__ void grid_sync() {
    __syncthreads();
    if (threadIdx.x == 0) {
        __threadfence();
        unsigned old = *(volatile unsigned*)&g_sense;  // read BEFORE arriving: no flip can
                                                       // happen until all 128 arrive
        unsigned v = atomicAdd(&g_cnt, 1u);
        if (v == NCTA - 1) {
            atomicExch(&g_cnt, 0u);
            __threadfence();
            atomicExch(&g_sense, old ^ 1u);
        } else {
            while (*(volatile unsigned*)&g_sense == old) {
                __nanosleep(64);
            }
        }
        __threadfence();
    }
    __syncthreads();
}

// Shared-tile strides: pad 34 keeps float2 reads 8B-aligned (34 even) and
// limits transposed-store conflicts to 2-way (34 mod 32 == 2).
#define SW 34

__global__ void __launch_bounds__(NTHR, 1)
ode_kernel(const float* __restrict__ X,       // (B,T,I)
           const float* __restrict__ hidden,  // (B,H)
           const float* __restrict__ alpha,   // (1,)
           const float* __restrict__ bias,    // (H,)
           const float* __restrict__ Wh,      // (H,H)
           const float* __restrict__ Wx,      // (I,H)
           const float* __restrict__ fcw,     // (H,C)
           const float* __restrict__ fcb,     // (C,)
           float* __restrict__ out,           // (B*T, C) [+ optional (B,H) h_final]
           int write_hf)
{
    __shared__ __align__(16) float Ast[32 * SW];   // [k][i] (transposed A tile)
    __shared__ __align__(16) float Bst[32 * SW];   // [k][j]
    __shared__ float red[8][C_];

    const int tid = threadIdx.x;
    const int bx  = blockIdx.x;
    const int r   = bx & 3;          // 4 row tiles of 32 (B=128)
    const int cb  = bx >> 2;         // 32 col tiles of 32 (H=1024)
    const int b0  = r * 32;
    const int j0  = cb * 32;
    const int ty  = tid >> 4;        // 0..15
    const int tx  = tid & 15;        // 0..15
    const int lk  = tid & 31;        // loader: k index (coalesced global)
    const int li  = tid >> 5;        // loader: row base (0..7)

    // init hidden state into buffer 0
    for (int i = bx * NTHR + tid; i < B_ * H_; i += NCTA * NTHR)
        g_h[0][i] = hidden[i];
    grid_sync();

    const float a = alpha[0];
    int cur = 0;

    for (int t = 0; t < T_; t++) {
        const float* __restrict__ hb = g_h[cur];

        // ---- FC for previous timestep's output (h after step t-1) ----
        if (t > 0) {
            const int bb = bx;  // CTA <-> batch row (128 each)
            float s[C_];
#pragma unroll
            for (int c = 0; c < C_; c++) s[c] = 0.f;
            for (int h = tid; h < H_; h += NTHR) {
                float hv = hb[bb * H_ + h];
                const float* w = fcw + h * C_;
#pragma unroll
                for (int c = 0; c < C_; c++) s[c] = fmaf(hv, w[c], s[c]);
            }
#pragma unroll
            for (int c = 0; c < C_; c++) {
#pragma unroll
                for (int off = 16; off > 0; off >>= 1)
                    s[c] += __shfl_xor_sync(0xffffffffu, s[c], off);
            }
            if ((tid & 31) == 0) {
#pragma unroll
                for (int c = 0; c < C_; c++) red[tid >> 5][c] = s[c];
            }
            __syncthreads();
            if (tid < C_) {
                float tot = fcb[tid];
#pragma unroll
                for (int w8 = 0; w8 < 8; w8++) tot += red[w8][tid];
                out[((size_t)bb * T_ + (t - 1)) * C_ + tid] = tot;
            }
            __syncthreads();
        }

        // ---- phase 1: Z = h @ Wh + x_t @ Wx + bias ----
        float a00 = 0.f, a01 = 0.f, a10 = 0.f, a11 = 0.f;
        for (int k0 = 0; k0 < H_; k0 += 32) {
            __syncthreads();
#pragma unroll
            for (int m = 0; m < 4; m++) {
                int i = li + 8 * m;
                Ast[lk * SW + i] = hb[(b0 + i) * H_ + k0 + lk];
                Bst[(li + 8 * m) * SW + lk] = Wh[(size_t)(k0 + li + 8 * m) * H_ + j0 + lk];
            }
            __syncthreads();
#pragma unroll
            for (int k = 0; k < 32; k++) {
                float2 av = *(const float2*)&Ast[k * SW + 2 * ty];
                float2 bv = *(const float2*)&Bst[k * SW + 2 * tx];
                a00 = fmaf(av.x, bv.x, a00); a01 = fmaf(av.x, bv.y, a01);
                a10 = fmaf(av.y, bv.x, a10); a11 = fmaf(av.y, bv.y, a11);
            }
        }
        for (int k0 = 0; k0 < I_; k0 += 32) {
            __syncthreads();
#pragma unroll
            for (int m = 0; m < 4; m++) {
                int i = li + 8 * m;
                Ast[lk * SW + i] = X[((size_t)(b0 + i) * T_ + t) * I_ + k0 + lk];
                Bst[(li + 8 * m) * SW + lk] = Wx[(size_t)(k0 + li + 8 * m) * H_ + j0 + lk];
            }
            __syncthreads();
#pragma unroll
            for (int k = 0; k < 32; k++) {
                float2 av = *(const float2*)&Ast[k * SW + 2 * ty];
                float2 bv = *(const float2*)&Bst[k * SW + 2 * tx];
                a00 = fmaf(av.x, bv.x, a00); a01 = fmaf(av.x, bv.y, a01);
                a10 = fmaf(av.y, bv.x, a10); a11 = fmaf(av.y, bv.y, a11);
            }
        }
        {
            int row = b0 + 2 * ty, col = j0 + 2 * tx;
            float bz0 = bias[col], bz1 = bias[col + 1];
            g_z[row * H_ + col]           = a00 + bz0;
            g_z[row * H_ + col + 1]       = a01 + bz1;
            g_z[(row + 1) * H_ + col]     = a10 + bz0;
            g_z[(row + 1) * H_ + col + 1] = a11 + bz1;
        }
        grid_sync();

        // ---- phase 2: G = v @ Wh^T with v = a*h - relu(Z); h update ----
        float c00 = 0.f, c01 = 0.f, c10 = 0.f, c11 = 0.f;
        for (int k0 = 0; k0 < H_; k0 += 32) {
            __syncthreads();
#pragma unroll
            for (int m = 0; m < 4; m++) {
                int i = li + 8 * m;
                int gi = (b0 + i) * H_ + k0 + lk;
                float hv = hb[gi];
                float z  = g_z[gi];
                Ast[lk * SW + i] = fmaf(a, hv, -fmaxf(z, 0.f));
                // B tile = Wh rows (Wh^T columns): Bst[k][j] = Wh[j0+j][k0+k]
                Bst[lk * SW + (li + 8 * m)] = Wh[(size_t)(j0 + li + 8 * m) * H_ + k0 + lk];
            }
            __syncthreads();
#pragma unroll
            for (int k = 0; k < 32; k++) {
                float2 av = *(const float2*)&Ast[k * SW + 2 * ty];
                float2 bv = *(const float2*)&Bst[k * SW + 2 * tx];
                c00 = fmaf(av.x, bv.x, c00); c01 = fmaf(av.x, bv.y, c01);
                c10 = fmaf(av.y, bv.x, c10); c11 = fmaf(av.y, bv.y, c11);
            }
        }
        {
            float* __restrict__ hn = g_h[cur ^ 1];
            int row = b0 + 2 * ty, col = j0 + 2 * tx;
#pragma unroll
            for (int di = 0; di < 2; di++) {
#pragma unroll
                for (int dj = 0; dj < 2; dj++) {
                    float G = (di == 0) ? (dj == 0 ? c00 : c01) : (dj == 0 ? c10 : c11);
                    int gi = (row + di) * H_ + (col + dj);
                    float z  = g_z[gi];
                    float hv = hb[gi];
                    float vj = fmaf(a, hv, -fmaxf(z, 0.f));
                    float grad = a * vj - (z > 0.f ? G : 0.f);
                    hn[gi] = fmaf(-LRC, grad, hv);
                }
            }
        }
        grid_sync();
        cur ^= 1;
    }

    // ---- final FC (t = T-1) + optional h_final tail ----
    {
        const float* __restrict__ hb = g_h[cur];
        const int bb = bx;
        float s[C_];
#pragma unroll
        for (int c = 0; c < C_; c++) s[c] = 0.f;
        for (int h = tid; h < H_; h += NTHR) {
            float hv = hb[bb * H_ + h];
            const float* w = fcw + h * C_;
#pragma unroll
            for (int c = 0; c < C_; c++) s[c] = fmaf(hv, w[c], s[c]);
        }
#pragma unroll
        for (int c = 0; c < C_; c++) {
#pragma unroll
            for (int off = 16; off > 0; off >>= 1)
                s[c] += __shfl_xor_sync(0xffffffffu, s[c], off);
        }
        if ((tid & 31) == 0) {
#pragma unroll
            for (int c = 0; c < C_; c++) red[tid >> 5][c] = s[c];
        }
        __syncthreads();
        if (tid < C_) {
            float tot = fcb[tid];
#pragma unroll
            for (int w8 = 0; w8 < 8; w8++) tot += red[w8][tid];
            out[((size_t)bb * T_ + (T_ - 1)) * C_ + tid] = tot;
        }

        if (write_hf) {
            for (int i = bx * NTHR + tid; i < B_ * H_; i += NCTA * NTHR)
                out[(size_t)B_ * T_ * C_ + i] = hb[i];
        }
    }
}

extern "C" void kernel_launch(void* const* d_in, const int* in_sizes, int n_in,
                              void* d_out, int out_size) {
    // Map inputs by element count (all sizes are distinct for this problem).
    const float *X = 0, *hid = 0, *al = 0, *bi = 0, *Wh = 0, *Wx = 0, *fw = 0, *fb = 0;
    for (int i = 0; i < n_in; i++) {
        const float* p = (const float*)d_in[i];
        switch (in_sizes[i]) {
            case B_ * T_ * I_: X   = p; break;  // 8388608
            case B_ * H_:      hid = p; break;  // 131072
            case 1:            al  = p; break;
            case H_:           bi  = p; break;  // 1024
            case H_ * H_:      Wh  = p; break;  // 1048576
            case I_ * H_:      Wx  = p; break;  // 262144
            case H_ * C_:      fw  = p; break;  // 10240
            case C_:           fb  = p; break;  // 10
            default: break;
        }
    }
    int write_hf = (out_size >= B_ * T_ * C_ + B_ * H_) ? 1 : 0;
    ode_kernel<<<NCTA, NTHR>>>(X, hid, al, bi, Wh, Wx, fw, fb, (float*)d_out, write_hf);
}

// round 8
// speedup vs baseline: 1.4208x; 1.4208x over previous
#include <cuda_runtime.h>

// Problem constants
#define B_   128
#define T_   256
#define I_   256
#define H_   1024
#define C_   10
#define LRC  0.001f

#define NCTA 128
#define NTHR 512          // 4 split-K teams x 128 threads
#define AW   34           // A tile row stride (floats): even (8B-aligned LDS.64), 2-way store conflict
#define BW   34           // B tile row stride (float2): even => 16B-aligned LDS.128
#define RW   33           // reduction buffer row stride (floats)

// ---------------- device scratch (no allocs allowed) ----------------
__device__ float g_h[2][B_ * H_];     // double-buffered hidden state
__device__ float g_z[B_ * H_];        // pre-activation Z per step
__device__ float g_WhT[H_ * H_];      // Wh transposed (built once per launch)
__device__ unsigned g_cnt = 0;
__device__ unsigned g_sense = 0;

// Sense-reversing grid barrier. 128 CTAs <= 148 SMs, all co-resident.
__device__ __forceinline__ void grid_sync() {
    __syncthreads();
    if (threadIdx.x == 0) {
        __threadfence();
        unsigned old = *(volatile unsigned*)&g_sense;
        unsigned v = atomicAdd(&g_cnt, 1u);
        if (v == NCTA - 1) {
            atomicExch(&g_cnt, 0u);
            __threadfence();
            atomicExch(&g_sense, old ^ 1u);
        } else {
            while (*(volatile unsigned*)&g_sense == old) { __nanosleep(64); }
        }
        __threadfence();
    }
    __syncthreads();
}

// Packed f32x2 FMA (SASS FFMA2): 2 MACs per FMA-pipe slot.
__device__ __forceinline__ unsigned long long ffma2(unsigned long long a,
                                                    unsigned long long b,
                                                    unsigned long long c) {
    unsigned long long d;
    asm("fma.rn.f32x2 %0, %1, %2, %3;" : "=l"(d) : "l"(a), "l"(b), "l"(c));
    return d;
}

union F2U { unsigned long long u; float2 f; };

extern __shared__ char sbuf[];
// layout: Ast: 4 teams x 32*AW floats   = 17408 B   (overlapped by red: 4*32*RW*4 = 16896 B)
//         Bst: 4 teams x 32*BW float2   = 34816 B   (at offset 17408)
#define DYN_SMEM 52224

__global__ void __launch_bounds__(NTHR, 1)
ode_kernel(const float* __restrict__ X,       // (B,T,I)
           const float* __restrict__ hidden,  // (B,H)
           const float* __restrict__ alpha,   // (1,)
           const float* __restrict__ bias,    // (H,)
           const float* __restrict__ Wh,      // (H,H)
           const float* __restrict__ Wx,      // (I,H)
           const float* __restrict__ fcw,     // (H,C)
           const float* __restrict__ fcb,     // (C,)
           float* __restrict__ out,           // (B*T, C) [+ optional (B,H) h_final]
           int write_hf)
{
    __shared__ float fcred[16][C_];

    const int tid  = threadIdx.x;
    const int bx   = blockIdx.x;
    const int team = tid >> 7;        // 0..3 (split-K team)
    const int wt   = tid & 127;       // thread within team
    const int b0   = (bx & 3) * 32;   // batch-row tile base
    const int jb   = (bx >> 2) * 32;  // hidden-col tile base
    // compute map: 2x4 micro-tile (rows i0,i0+1; cols jc..jc+3)
    const int ty = wt & 15, tx = wt >> 4;
    const int i0 = 2 * ty, jc = 4 * tx;
    // loader map: lanes vary fastest index for coalesced LDG
    const int lk = wt & 31, li = wt >> 5;   // A: k lane, row base (0..3)
    const int lj = wt & 31, l4 = wt >> 5;   // B: j lane, k base (0..3)

    float*  Ast = (float*)sbuf + team * (32 * AW);
    float2* Bst = (float2*)(sbuf + 17408) + team * (32 * BW);
    float*  red = (float*)sbuf;             // [4][32*RW] overlaps Ast region

    // ---- one-time init: copy h0, transpose Wh ----
    for (int i = bx * NTHR + tid; i < B_ * H_; i += NCTA * NTHR)
        g_h[0][i] = hidden[i];
    for (int i = bx * NTHR + tid; i < H_ * H_; i += NCTA * NTHR) {
        int rr = i >> 10, cc = i & (H_ - 1);
        g_WhT[(size_t)cc * H_ + rr] = Wh[i];
    }
    grid_sync();

    const float a = alpha[0];
    int cur = 0;

    for (int t = 0; t < T_; t++) {
        const float* __restrict__ hb = g_h[cur];

        // ---- FC for previous step's hidden state ----
        if (t > 0) {
            const int bb = bx;
            float s[C_];
#pragma unroll
            for (int c = 0; c < C_; c++) s[c] = 0.f;
            for (int h = tid; h < H_; h += NTHR) {
                float hv = hb[bb * H_ + h];
                const float* w = fcw + h * C_;
#pragma unroll
                for (int c = 0; c < C_; c++) s[c] = fmaf(hv, w[c], s[c]);
            }
#pragma unroll
            for (int c = 0; c < C_; c++) {
#pragma unroll
                for (int off = 16; off > 0; off >>= 1)
                    s[c] += __shfl_xor_sync(0xffffffffu, s[c], off);
            }
            if ((tid & 31) == 0) {
#pragma unroll
                for (int c = 0; c < C_; c++) fcred[tid >> 5][c] = s[c];
            }
            __syncthreads();
            if (tid < C_) {
                float tot = fcb[tid];
#pragma unroll
                for (int w16 = 0; w16 < 16; w16++) tot += fcred[w16][tid];
                out[((size_t)bb * T_ + (t - 1)) * C_ + tid] = tot;
            }
            __syncthreads();
        }

        float pa[8], pb[8];
        unsigned long long acc0, acc1, acc2, acc3;

        auto store_tiles = [&]() {
#pragma unroll
            for (int m = 0; m < 8; m++) Ast[lk * AW + li + 4 * m] = pa[m];
#pragma unroll
            for (int m = 0; m < 8; m++)
                Bst[(l4 + 4 * m) * BW + lj] = make_float2(pb[m], pb[m]);
        };
        auto compute32 = [&]() {
#pragma unroll
            for (int k = 0; k < 32; k++) {
                unsigned long long av =
                    *(const unsigned long long*)(Ast + k * AW + i0);
                ulonglong2 bq0 = *(const ulonglong2*)(Bst + k * BW + jc);
                ulonglong2 bq1 = *(const ulonglong2*)(Bst + k * BW + jc + 2);
                acc0 = ffma2(av, bq0.x, acc0);
                acc1 = ffma2(av, bq0.y, acc1);
                acc2 = ffma2(av, bq1.x, acc2);
                acc3 = ffma2(av, bq1.y, acc3);
            }
        };
        auto write_red = [&]() {
            F2U c;
            c.u = acc0; red[team * (32 * RW) + i0 * RW + jc]           = c.f.x;
                        red[team * (32 * RW) + (i0 + 1) * RW + jc]     = c.f.y;
            c.u = acc1; red[team * (32 * RW) + i0 * RW + jc + 1]       = c.f.x;
                        red[team * (32 * RW) + (i0 + 1) * RW + jc + 1] = c.f.y;
            c.u = acc2; red[team * (32 * RW) + i0 * RW + jc + 2]       = c.f.x;
                        red[team * (32 * RW) + (i0 + 1) * RW + jc + 2] = c.f.y;
            c.u = acc3; red[team * (32 * RW) + i0 * RW + jc + 3]       = c.f.x;
                        red[team * (32 * RW) + (i0 + 1) * RW + jc + 3] = c.f.y;
        };

        // ================= phase 1: Z = h@Wh + x@Wx + b =================
        acc0 = acc1 = acc2 = acc3 = 0ull;
        auto pref1 = [&](int tt) {
            if (tt < 32) {
                int k0 = tt * 32;
#pragma unroll
                for (int m = 0; m < 8; m++)
                    pa[m] = hb[(b0 + li + 4 * m) * H_ + k0 + lk];
#pragma unroll
                for (int m = 0; m < 8; m++)
                    pb[m] = Wh[(size_t)(k0 + l4 + 4 * m) * H_ + jb + lj];
            } else {
                int k0 = (tt - 32) * 32;
#pragma unroll
                for (int m = 0; m < 8; m++)
                    pa[m] = X[((size_t)(b0 + li + 4 * m) * T_ + t) * I_ + k0 + lk];
#pragma unroll
                for (int m = 0; m < 8; m++)
                    pb[m] = Wx[(size_t)(k0 + l4 + 4 * m) * H_ + jb + lj];
            }
        };
        pref1(team);
        for (int it = 0; it < 10; it++) {   // 40 k-tiles / 4 teams
            __syncthreads();
            store_tiles();
            __syncthreads();
            if (it < 9) pref1(team + 4 * (it + 1));
            compute32();
        }
        __syncthreads();
        write_red();
        __syncthreads();
#pragma unroll
        for (int q = 0; q < 2; q++) {       // epilogue: sum teams + bias -> g_z
            int idx = tid + q * NTHR;
            int i = idx >> 5, j = idx & 31;
            float s = red[i * RW + j] + red[32 * RW + i * RW + j] +
                      red[64 * RW + i * RW + j] + red[96 * RW + i * RW + j];
            g_z[(b0 + i) * H_ + jb + j] = s + bias[jb + j];
        }
        grid_sync();

        // ============ phase 2: G = v @ Wh^T, v = a*h - relu(Z) ============
        acc0 = acc1 = acc2 = acc3 = 0ull;
        auto pref2 = [&](int tt) {
            int k0 = tt * 32;
#pragma unroll
            for (int m = 0; m < 8; m++) {
                int gi = (b0 + li + 4 * m) * H_ + k0 + lk;
                pa[m] = fmaf(a, hb[gi], -fmaxf(g_z[gi], 0.f));
            }
#pragma unroll
            for (int m = 0; m < 8; m++)
                pb[m] = g_WhT[(size_t)(k0 + l4 + 4 * m) * H_ + jb + lj];
        };
        pref2(team);
        for (int it = 0; it < 8; it++) {    // 32 k-tiles / 4 teams
            __syncthreads();
            store_tiles();
            __syncthreads();
            if (it < 7) pref2(team + 4 * (it + 1));
            compute32();
        }
        __syncthreads();
        write_red();
        __syncthreads();
        {
            float* __restrict__ hn = g_h[cur ^ 1];
#pragma unroll
            for (int q = 0; q < 2; q++) {   // epilogue: h update
                int idx = tid + q * NTHR;
                int i = idx >> 5, j = idx & 31;
                float G = red[i * RW + j] + red[32 * RW + i * RW + j] +
                          red[64 * RW + i * RW + j] + red[96 * RW + i * RW + j];
                int gi = (b0 + i) * H_ + jb + j;
                float z = g_z[gi], hv = hb[gi];
                float v = fmaf(a, hv, -fmaxf(z, 0.f));
                float grad = a * v - (z > 0.f ? G : 0.f);
                hn[gi] = fmaf(-LRC, grad, hv);
            }
        }
        grid_sync();
        cur ^= 1;
    }

    // ---- final FC (t = T-1) + optional h_final tail ----
    {
        const float* __restrict__ hb = g_h[cur];
        const int bb = bx;
        float s[C_];
#pragma unroll
        for (int c = 0; c < C_; c++) s[c] = 0.f;
        for (int h = tid; h < H_; h += NTHR) {
            float hv = hb[bb * H_ + h];
            const float* w = fcw + h * C_;
#pragma unroll
            for (int c = 0; c < C_; c++) s[c] = fmaf(hv, w[c], s[c]);
        }
#pragma unroll
        for (int c = 0; c < C_; c++) {
#pragma unroll
            for (int off = 16; off > 0; off >>= 1)
                s[c] += __shfl_xor_sync(0xffffffffu, s[c], off);
        }
        if ((tid & 31) == 0) {
#pragma unroll
            for (int c = 0; c < C_; c++) fcred[tid >> 5][c] = s[c];
        }
        __syncthreads();
        if (tid < C_) {
            float tot = fcb[tid];
#pragma unroll
            for (int w16 = 0; w16 < 16; w16++) tot += fcred[w16][tid];
            out[((size_t)bb * T_ + (T_ - 1)) * C_ + tid] = tot;
        }
        if (write_hf) {
            for (int i = bx * NTHR + tid; i < B_ * H_; i += NCTA * NTHR)
                out[(size_t)B_ * T_ * C_ + i] = hb[i];
        }
    }
}

extern "C" void kernel_launch(void* const* d_in, const int* in_sizes, int n_in,
                              void* d_out, int out_size) {
    const float *X = 0, *hid = 0, *al = 0, *bi = 0, *Wh = 0, *Wx = 0, *fw = 0, *fb = 0;
    for (int i = 0; i < n_in; i++) {
        const float* p = (const float*)d_in[i];
        switch (in_sizes[i]) {
            case B_ * T_ * I_: X   = p; break;
            case B_ * H_:      hid = p; break;
            case 1:            al  = p; break;
            case H_:           bi  = p; break;
            case H_ * H_:      Wh  = p; break;
            case I_ * H_:      Wx  = p; break;
            case H_ * C_:      fw  = p; break;
            case C_:           fb  = p; break;
            default: break;
        }
    }
    // Not an allocation; executes immediately (legal during graph capture).
    cudaFuncSetAttribute(ode_kernel, cudaFuncAttributeMaxDynamicSharedMemorySize,
                         DYN_SMEM);
    int write_hf = (out_size >= B_ * T_ * C_ + B_ * H_) ? 1 : 0;
    ode_kernel<<<NCTA, NTHR, DYN_SMEM>>>(X, hid, al, bi, Wh, Wx, fw, fb,
                                         (float*)d_out, write_hf);
}

// round 12
// speedup vs baseline: 1.7033x; 1.1988x over previous
#include <cuda_runtime.h>
#include <cstdint>

// Problem constants
#define B_   128
#define T_   256
#define I_   256
#define H_   1024
#define C_   10
#define LRC  0.001f

#define NCTA 128
#define NTHR 256              // 8 warps = 8 split-K teams
#define NTEAM 8
#define TW    36              // tile row stride (floats) = 144 B (16B-aligned rows)
#define TILE_F (32 * TW)      // 1152 floats = 4608 B per tile
#define STAGE_F (2 * TILE_F)  // A + B
#define RED_OFF_F (NTEAM * 2 * STAGE_F)  // after 8 teams x 2 stages
#define REDW  34
#define RED_TEAM_F (32 * REDW)
#define DYN_SMEM ((RED_OFF_F + NTEAM * RED_TEAM_F) * 4)  // 182272 B

// ---------------- device scratch (no allocs allowed) ----------------
__device__ float g_h[2][B_ * H_];   // double-buffered hidden state
__device__ float g_z[B_ * H_];      // pre-activation Z
__device__ float g_v[B_ * H_];      // v = a*h - relu(Z) (phase-2 A operand)
__device__ float g_WhT[H_ * H_];    // Wh transposed (built once per launch)
__device__ unsigned g_cnt = 0;
__device__ unsigned g_sense = 0;

// Sense-reversing grid barrier. 128 CTAs <= 148 SMs, all co-resident.
__device__ __forceinline__ void grid_sync() {
    __syncthreads();
    if (threadIdx.x == 0) {
        __threadfence();
        unsigned old = *(volatile unsigned*)&g_sense;
        unsigned v = atomicAdd(&g_cnt, 1u);
        if (v == NCTA - 1) {
            atomicExch(&g_cnt, 0u);
            __threadfence();
            atomicExch(&g_sense, old ^ 1u);
        } else {
            while (*(volatile unsigned*)&g_sense == old) { __nanosleep(64); }
        }
        __threadfence();
    }
    __syncthreads();
}

// Packed f32x2 FMA (SASS FFMA2): 2 MACs per FMA-pipe slot.
__device__ __forceinline__ unsigned long long ffma2(unsigned long long a,
                                                    unsigned long long b,
                                                    unsigned long long c) {
    unsigned long long d;
    asm("fma.rn.f32x2 %0, %1, %2, %3;" : "=l"(d) : "l"(a), "l"(b), "l"(c));
    return d;
}
union F2U { unsigned long long u; float2 f; };

__device__ __forceinline__ void cp16(uint32_t dst, const float* src) {
    asm volatile("cp.async.cg.shared.global [%0], [%1], 16;"
                 :: "r"(dst), "l"(src) : "memory");
}
#define CP_COMMIT() asm volatile("cp.async.commit_group;" ::: "memory")
#define CP_WAIT(n)  asm volatile("cp.async.wait_group %0;" :: "n"(n) : "memory")

extern __shared__ float smf[];

__global__ void __launch_bounds__(NTHR, 1)
ode_kernel(const float* __restrict__ X,       // (B,T,I)
           const float* __restrict__ hidden,  // (B,H)
           const float* __restrict__ alpha,   // (1,)
           const float* __restrict__ bias,    // (H,)
           const float* __restrict__ Wh,      // (H,H)
           const float* __restrict__ Wx,      // (I,H)
           const float* __restrict__ fcw,     // (H,C)
           const float* __restrict__ fcb,     // (C,)
           float* __restrict__ out,           // (B*T, C) [+ optional (B,H)]
           int write_hf)
{
    __shared__ float fcred[8][C_];

    const int tid  = threadIdx.x;
    const int bx   = blockIdx.x;
    const int s    = tid >> 5;        // team = warp id (0..7)
    const int lane = tid & 31;
    const int ty   = lane & 7;        // row group: rows ty + 8m
    const int tx   = lane >> 3;       // col group: cols 8*tx .. 8*tx+7
    const int j0   = 8 * tx;
    const int b0   = (bx & 3) * 32;   // batch-row tile base
    const int jb   = (bx >> 2) * 32;  // hidden-col tile base

    const uint32_t smem_u32 = (uint32_t)__cvta_generic_to_shared(smf);
    // per-lane destination row bases for the two stages
    uint32_t dA[2], dB[2];
#pragma unroll
    for (int p = 0; p < 2; p++) {
        uint32_t base = smem_u32 + (uint32_t)((s * 2 + p) * STAGE_F) * 4u;
        dA[p] = base + (uint32_t)lane * (TW * 4);
        dB[p] = base + (uint32_t)TILE_F * 4 + (uint32_t)lane * (TW * 4);
    }

    // ---- one-time init: copy h0, transpose Wh ----
    for (int i = bx * NTHR + tid; i < B_ * H_; i += NCTA * NTHR)
        g_h[0][i] = hidden[i];
    for (int i = bx * NTHR + tid; i < H_ * H_; i += NCTA * NTHR) {
        int rr = i >> 10, cc = i & (H_ - 1);
        g_WhT[(size_t)cc * H_ + rr] = Wh[i];
    }
    grid_sync();

    const float a = alpha[0];
    int cur = 0;

    // load one 32x32 A tile (row-major: Ast[row*TW + k]) and one B tile
    // (k-major: Bst[k*TW + j]) into stage p via cp.async
    auto load_tile = [&](const float* srcA, size_t strA,
                         const float* srcB, size_t strB, int p) {
        const float* sa = srcA + (size_t)lane * strA;  // lane = A row
        const float* sb = srcB + (size_t)lane * strB;  // lane = B k-row
#pragma unroll
        for (int c = 0; c < 8; c++) cp16(dA[p] + 16 * c, sa + 4 * c);
#pragma unroll
        for (int c = 0; c < 8; c++) cp16(dB[p] + 16 * c, sb + 4 * c);
        CP_COMMIT();
    };

    unsigned long long acc[16];

    auto compute = [&](int p) {
        const float* Ast = smf + (s * 2 + p) * STAGE_F;
        const float* Bst = Ast + TILE_F;
#pragma unroll
        for (int k = 0; k < 32; k++) {
            // A is row-major in smem: row (ty+8m), col k.
            // Bank = (4*ty + k) mod 32: 8 distinct banks, 4-way broadcast.
            float a0 = Ast[ty * TW + k];
            float a1 = Ast[(ty + 8) * TW + k];
            float a2 = Ast[(ty + 16) * TW + k];
            float a3 = Ast[(ty + 24) * TW + k];
            ulonglong2 q0 = *(const ulonglong2*)(Bst + k * TW + j0);
            ulonglong2 q1 = *(const ulonglong2*)(Bst + k * TW + j0 + 4);
            F2U d0, d1, d2, d3;
            d0.f = make_float2(a0, a0); d1.f = make_float2(a1, a1);
            d2.f = make_float2(a2, a2); d3.f = make_float2(a3, a3);
            acc[0]  = ffma2(d0.u, q0.x, acc[0]);
            acc[1]  = ffma2(d0.u, q0.y, acc[1]);
            acc[2]  = ffma2(d0.u, q1.x, acc[2]);
            acc[3]  = ffma2(d0.u, q1.y, acc[3]);
            acc[4]  = ffma2(d1.u, q0.x, acc[4]);
            acc[5]  = ffma2(d1.u, q0.y, acc[5]);
            acc[6]  = ffma2(d1.u, q1.x, acc[6]);
            acc[7]  = ffma2(d1.u, q1.y, acc[7]);
            acc[8]  = ffma2(d2.u, q0.x, acc[8]);
            acc[9]  = ffma2(d2.u, q0.y, acc[9]);
            acc[10] = ffma2(d2.u, q1.x, acc[10]);
            acc[11] = ffma2(d2.u, q1.y, acc[11]);
            acc[12] = ffma2(d3.u, q0.x, acc[12]);
            acc[13] = ffma2(d3.u, q0.y, acc[13]);
            acc[14] = ffma2(d3.u, q1.x, acc[14]);
            acc[15] = ffma2(d3.u, q1.y, acc[15]);
        }
    };

    auto write_red = [&]() {
        float* rp = smf + RED_OFF_F + s * RED_TEAM_F;
#pragma unroll
        for (int m = 0; m < 4; m++) {
            int row = ty + 8 * m;
#pragma unroll
            for (int pp = 0; pp < 4; pp++) {
                F2U c; c.u = acc[m * 4 + pp];
                *(float2*)&rp[row * REDW + j0 + 2 * pp] = c.f;
            }
        }
    };

    for (int t = 0; t < T_; t++) {
        const float* __restrict__ hb = g_h[cur];

        // phase-1 tile spec for this team's idx-th k-tile (idx 0..4)
        auto spec1 = [&](int idx, const float*& sA, size_t& strA,
                         const float*& sB, size_t& strB) {
            int tt = s + 8 * idx;
            if (tt < 32) {
                int k0 = tt * 32;
                sA = hb + (size_t)b0 * H_ + k0;          strA = H_;
                sB = Wh + (size_t)k0 * H_ + jb;          strB = H_;
            } else {
                int k0 = (tt - 32) * 32;
                sA = X + ((size_t)b0 * T_ + t) * I_ + k0; strA = (size_t)T_ * I_;
                sB = Wx + (size_t)k0 * H_ + jb;           strB = H_;
            }
        };

        // prologue: issue tile 0 now, overlap its latency with the FC below
        {
            const float *sA, *sB; size_t strA, strB;
            spec1(0, sA, strA, sB, strB);
            load_tile(sA, strA, sB, strB, 0);
        }

        // ---- FC for previous step's hidden state ----
        if (t > 0) {
            const int bb = bx;
            float sfc[C_];
#pragma unroll
            for (int c = 0; c < C_; c++) sfc[c] = 0.f;
            for (int h = tid; h < H_; h += NTHR) {
                float hv = hb[bb * H_ + h];
                const float* w = fcw + h * C_;
#pragma unroll
                for (int c = 0; c < C_; c++) sfc[c] = fmaf(hv, w[c], sfc[c]);
            }
#pragma unroll
            for (int c = 0; c < C_; c++) {
#pragma unroll
                for (int off = 16; off > 0; off >>= 1)
                    sfc[c] += __shfl_xor_sync(0xffffffffu, sfc[c], off);
            }
            if (lane == 0) {
#pragma unroll
                for (int c = 0; c < C_; c++) fcred[s][c] = sfc[c];
            }
            __syncthreads();
            if (tid < C_) {
                float tot = fcb[tid];
#pragma unroll
                for (int w8 = 0; w8 < 8; w8++) tot += fcred[w8][tid];
                out[((size_t)bb * T_ + (t - 1)) * C_ + tid] = tot;
            }
        }

        // ================= phase 1: Z = h@Wh + x@Wx + b =================
#pragma unroll
        for (int i = 0; i < 16; i++) acc[i] = 0ull;
#pragma unroll 1
        for (int it = 0; it < 5; it++) {
            if (it < 4) {
                const float *sA, *sB; size_t strA, strB;
                spec1(it + 1, sA, strA, sB, strB);
                load_tile(sA, strA, sB, strB, (it + 1) & 1);
                CP_WAIT(1);
            } else {
                CP_WAIT(0);
            }
            __syncthreads();
            compute(it & 1);
        }
        write_red();
        __syncthreads();
#pragma unroll
        for (int q = 0; q < 4; q++) {       // epilogue: sum teams, write z & v
            int o = q * NTHR + tid;
            int i = o >> 5, j = o & 31;
            float sum = 0.f;
#pragma unroll
            for (int ss = 0; ss < 8; ss++)
                sum += smf[RED_OFF_F + ss * RED_TEAM_F + i * REDW + j];
            int gi = (b0 + i) * H_ + jb + j;
            float z = sum + bias[jb + j];
            g_z[gi] = z;
            g_v[gi] = fmaf(a, hb[gi], -fmaxf(z, 0.f));
        }
        grid_sync();

        // ============ phase 2: G = v @ Wh^T ============
#pragma unroll
        for (int i = 0; i < 16; i++) acc[i] = 0ull;
        {
            int k0 = s * 32;
            load_tile(g_v + (size_t)b0 * H_ + k0, H_,
                      g_WhT + (size_t)k0 * H_ + jb, H_, 0);
        }
#pragma unroll 1
        for (int it = 0; it < 4; it++) {
            if (it < 3) {
                int k0 = (s + 8 * (it + 1)) * 32;
                load_tile(g_v + (size_t)b0 * H_ + k0, H_,
                          g_WhT + (size_t)k0 * H_ + jb, H_, (it + 1) & 1);
                CP_WAIT(1);
            } else {
                CP_WAIT(0);
            }
            __syncthreads();
            compute(it & 1);
        }
        write_red();
        __syncthreads();
        {
            float* __restrict__ hn = g_h[cur ^ 1];
#pragma unroll
            for (int q = 0; q < 4; q++) {   // epilogue: h update
                int o = q * NTHR + tid;
                int i = o >> 5, j = o & 31;
                float G = 0.f;
#pragma unroll
                for (int ss = 0; ss < 8; ss++)
                    G += smf[RED_OFF_F + ss * RED_TEAM_F + i * REDW + j];
                int gi = (b0 + i) * H_ + jb + j;
                float z = g_z[gi], hv = hb[gi], v = g_v[gi];
                float grad = a * v - (z > 0.f ? G : 0.f);
                hn[gi] = fmaf(-LRC, grad, hv);
            }
        }
        grid_sync();
        cur ^= 1;
    }

    // ---- final FC (t = T-1) + optional h_final tail ----
    {
        const float* __restrict__ hb = g_h[cur];
        const int bb = bx;
        float sfc[C_];
#pragma unroll
        for (int c = 0; c < C_; c++) sfc[c] = 0.f;
        for (int h = tid; h < H_; h += NTHR) {
            float hv = hb[bb * H_ + h];
            const float* w = fcw + h * C_;
#pragma unroll
            for (int c = 0; c < C_; c++) sfc[c] = fmaf(hv, w[c], sfc[c]);
        }
#pragma unroll
        for (int c = 0; c < C_; c++) {
#pragma unroll
            for (int off = 16; off > 0; off >>= 1)
                sfc[c] += __shfl_xor_sync(0xffffffffu, sfc[c], off);
        }
        if (lane == 0) {
#pragma unroll
            for (int c = 0; c < C_; c++) fcred[s][c] = sfc[c];
        }
        __syncthreads();
        if (tid < C_) {
            float tot = fcb[tid];
#pragma unroll
            for (int w8 = 0; w8 < 8; w8++) tot += fcred[w8][tid];
            out[((size_t)bb * T_ + (T_ - 1)) * C_ + tid] = tot;
        }
        if (write_hf) {
            for (int i = bx * NTHR + tid; i < B_ * H_; i += NCTA * NTHR)
                out[(size_t)B_ * T_ * C_ + i] = hb[i];
        }
    }
}

extern "C" void kernel_launch(void* const* d_in, const int* in_sizes, int n_in,
                              void* d_out, int out_size) {
    const float *X = 0, *hid = 0, *al = 0, *bi = 0, *Wh = 0, *Wx = 0, *fw = 0, *fb = 0;
    for (int i = 0; i < n_in; i++) {
        const float* p = (const float*)d_in[i];
        switch (in_sizes[i]) {
            case B_ * T_ * I_: X   = p; break;
            case B_ * H_:      hid = p; break;
            case 1:            al  = p; break;
            case H_:           bi  = p; break;
            case H_ * H_:      Wh  = p; break;
            case I_ * H_:      Wx  = p; break;
            case H_ * C_:      fw  = p; break;
            case C_:           fb  = p; break;
            default: break;
        }
    }
    cudaFuncSetAttribute(ode_kernel, cudaFuncAttributeMaxDynamicSharedMemorySize,
                         DYN_SMEM);
    int write_hf = (out_size >= B_ * T_ * C_ + B_ * H_) ? 1 : 0;
    ode_kernel<<<NCTA, NTHR, DYN_SMEM>>>(X, hid, al, bi, Wh, Wx, fw, fb,
                                         (float*)d_out, write_hf);
}

// round 16
// speedup vs baseline: 2.0953x; 1.2301x over previous
#include <cuda_runtime.h>
#include <cstdint>

// Problem constants
#define B_   128
#define T_   256
#define I_   256
#define H_   1024
#define C_   10
#define LRC  0.001f

#define NCTA  128
#define NTHR  512             // 16 warps = 16 split-K teams
#define NTEAM 16
#define KT    16              // k depth per tile
#define AW    20              // A tile row stride (floats); 80B rows (16B aligned, conflict-free)
#define A_F   (32 * AW)       // 640 floats
#define B_F   (KT * 32)       // 512 floats  (B tile [k][j], stride 32)
#define STAGE_F (A_F + B_F)   // 1152 floats = 4608 B
#define RED_OFF_F (NTEAM * 2 * STAGE_F)   // 36864 floats
#define REDW  34
#define RED_TEAM_F (32 * REDW)            // 1088 floats
#define DYN_SMEM ((RED_OFF_F + NTEAM * RED_TEAM_F) * 4)  // 217088 B

// ---------------- device scratch (no allocs allowed) ----------------
__device__ float g_h[2][B_ * H_];   // double-buffered hidden state
__device__ float g_z[B_ * H_];      // pre-activation Z
__device__ float g_v[B_ * H_];      // v = a*h - relu(Z)
__device__ float g_WhT[H_ * H_];    // Wh transposed (built once per launch)
__device__ unsigned g_cnt = 0, g_sense = 0;            // full-grid (init only)
__device__ unsigned g_cnt4[4]   = {0, 0, 0, 0};        // per-b-group barriers
__device__ unsigned g_sense4[4] = {0, 0, 0, 0};

// Full-grid sense barrier (used once after init).
__device__ __forceinline__ void full_sync() {
    __syncthreads();
    if (threadIdx.x == 0) {
        __threadfence();
        unsigned old = *(volatile unsigned*)&g_sense;
        unsigned v = atomicAdd(&g_cnt, 1u);
        if (v == NCTA - 1) {
            atomicExch(&g_cnt, 0u);
            __threadfence();
            atomicExch(&g_sense, old ^ 1u);
        } else {
            while (*(volatile unsigned*)&g_sense == old) { __nanosleep(32); }
        }
        __threadfence();
    }
    __syncthreads();
}

// 32-CTA group barrier: all cross-CTA dataflow is within a b-row group.
__device__ __forceinline__ void group_sync(int g) {
    __syncthreads();
    if (threadIdx.x == 0) {
        __threadfence();
        unsigned old = *(volatile unsigned*)&g_sense4[g];
        unsigned v = atomicAdd(&g_cnt4[g], 1u);
        if (v == 31) {
            atomicExch(&g_cnt4[g], 0u);
            __threadfence();
            atomicExch(&g_sense4[g], old ^ 1u);
        } else {
            while (*(volatile unsigned*)&g_sense4[g] == old) { __nanosleep(32); }
        }
        __threadfence();
    }
    __syncthreads();
}

// Packed f32x2 ops: 2 lanes of fp32 per FMA-pipe slot.
__device__ __forceinline__ unsigned long long ffma2(unsigned long long a,
                                                    unsigned long long b,
                                                    unsigned long long c) {
    unsigned long long d;
    asm("fma.rn.f32x2 %0, %1, %2, %3;" : "=l"(d) : "l"(a), "l"(b), "l"(c));
    return d;
}
__device__ __forceinline__ unsigned long long addf2(unsigned long long a,
                                                    unsigned long long b) {
    unsigned long long d;
    asm("add.rn.f32x2 %0, %1, %2;" : "=l"(d) : "l"(a), "l"(b));
    return d;
}
union F2U { unsigned long long u; float2 f; };

__device__ __forceinline__ void cp16(uint32_t dst, const float* src) {
    asm volatile("cp.async.cg.shared.global [%0], [%1], 16;"
                 :: "r"(dst), "l"(src) : "memory");
}
#define CP_COMMIT() asm volatile("cp.async.commit_group;" ::: "memory")
#define CP_WAIT(n)  asm volatile("cp.async.wait_group %0;" :: "n"(n) : "memory")

extern __shared__ float smf[];

__global__ void __launch_bounds__(NTHR, 1)
ode_kernel(const float* __restrict__ X,       // (B,T,I)
           const float* __restrict__ hidden,  // (B,H)
           const float* __restrict__ alpha,   // (1,)
           const float* __restrict__ bias,    // (H,)
           const float* __restrict__ Wh,      // (H,H)
           const float* __restrict__ Wx,      // (I,H)
           const float* __restrict__ fcw,     // (H,C)
           const float* __restrict__ fcb,     // (C,)
           float* __restrict__ out,           // (B*T, C) [+ optional (B,H)]
           int write_hf)
{
    __shared__ float fcred[NTEAM][C_];

    const int tid  = threadIdx.x;
    const int bx   = blockIdx.x;
    const int s    = tid >> 5;        // team = warp id (0..15)
    const int lane = tid & 31;
    const int ty   = lane & 7;        // rows ty + 8m, m=0..3
    const int tx   = lane >> 3;       // cols 8*tx .. 8*tx+7
    const int j0   = 8 * tx;
    const int grp  = bx & 3;          // b-row group
    const int b0   = grp * 32;        // batch-row tile base
    const int jb   = (bx >> 2) * 32;  // hidden-col tile base
    const int fcrow = b0 + (bx >> 2); // FC row owned by this CTA (group-local)

    const uint32_t smem_u32 = (uint32_t)__cvta_generic_to_shared(smf);
    uint32_t dA[2], dB[2];
#pragma unroll
    for (int p = 0; p < 2; p++) {
        uint32_t base = smem_u32 + (uint32_t)((s * 2 + p) * STAGE_F) * 4u;
        dA[p] = base + (uint32_t)lane * (AW * 4);                      // lane = A row
        dB[p] = base + (uint32_t)A_F * 4 +
                (uint32_t)(((lane >> 1) * 32 + (lane & 1) * 16) * 4);  // half k-rows
    }

    // ---- one-time init: copy h0, transpose Wh ----
    for (int i = bx * NTHR + tid; i < B_ * H_; i += NCTA * NTHR)
        g_h[0][i] = hidden[i];
    for (int i = bx * NTHR + tid; i < H_ * H_; i += NCTA * NTHR) {
        int rr = i >> 10, cc = i & (H_ - 1);
        g_WhT[(size_t)cc * H_ + rr] = Wh[i];
    }
    full_sync();

    const float a = alpha[0];
    int cur = 0;

    // A tile: 32 rows x KT floats, row-major stride AW. lane = row.
    auto cpA = [&](const float* srcA, size_t strA, int p) {
        const float* sa = srcA + (size_t)lane * strA;
        uint32_t d = dA[p];
        cp16(d, sa); cp16(d + 16, sa + 4); cp16(d + 32, sa + 8); cp16(d + 48, sa + 12);
    };
    // B tile: KT k-rows x 32 floats, stride 32. lane covers half a k-row (64B).
    auto cpB = [&](const float* srcB, size_t strB, int p) {
        const float* sb = srcB + (size_t)(lane >> 1) * strB + (lane & 1) * 16;
        uint32_t d = dB[p];
        cp16(d, sb); cp16(d + 16, sb + 4); cp16(d + 32, sb + 8); cp16(d + 48, sb + 12);
    };

    unsigned long long acc[16];

    auto compute = [&](int p) {
        const float* Ast = smf + (s * 2 + p) * STAGE_F;
        const float* Bst = Ast + A_F;
#pragma unroll
        for (int k = 0; k < KT; k++) {
            float a0 = Ast[ty * AW + k];
            float a1 = Ast[(ty + 8) * AW + k];
            float a2 = Ast[(ty + 16) * AW + k];
            float a3 = Ast[(ty + 24) * AW + k];
            ulonglong2 q0 = *(const ulonglong2*)(Bst + k * 32 + j0);
            ulonglong2 q1 = *(const ulonglong2*)(Bst + k * 32 + j0 + 4);
            F2U d0, d1, d2, d3;
            d0.f = make_float2(a0, a0); d1.f = make_float2(a1, a1);
            d2.f = make_float2(a2, a2); d3.f = make_float2(a3, a3);
            acc[0]  = ffma2(d0.u, q0.x, acc[0]);
            acc[1]  = ffma2(d0.u, q0.y, acc[1]);
            acc[2]  = ffma2(d0.u, q1.x, acc[2]);
            acc[3]  = ffma2(d0.u, q1.y, acc[3]);
            acc[4]  = ffma2(d1.u, q0.x, acc[4]);
            acc[5]  = ffma2(d1.u, q0.y, acc[5]);
            acc[6]  = ffma2(d1.u, q1.x, acc[6]);
            acc[7]  = ffma2(d1.u, q1.y, acc[7]);
            acc[8]  = ffma2(d2.u, q0.x, acc[8]);
            acc[9]  = ffma2(d2.u, q0.y, acc[9]);
            acc[10] = ffma2(d2.u, q1.x, acc[10]);
            acc[11] = ffma2(d2.u, q1.y, acc[11]);
            acc[12] = ffma2(d3.u, q0.x, acc[12]);
            acc[13] = ffma2(d3.u, q0.y, acc[13]);
            acc[14] = ffma2(d3.u, q1.x, acc[14]);
            acc[15] = ffma2(d3.u, q1.y, acc[15]);
        }
    };

    auto write_red = [&]() {
        float* rp = smf + RED_OFF_F + s * RED_TEAM_F;
#pragma unroll
        for (int m = 0; m < 4; m++) {
            int row = ty + 8 * m;
#pragma unroll
            for (int pp = 0; pp < 4; pp++) {
                F2U c; c.u = acc[m * 4 + pp];
                *(float2*)&rp[row * REDW + j0 + 2 * pp] = c.f;
            }
        }
    };

    // packed 16-team reduction for the output element pair owned by this thread
    const int ri = tid >> 4;            // 0..31 (tile row)
    const int rj = (tid & 15) * 2;      // 0..30 (tile col pair)
    auto reduce_pair = [&]() -> F2U {
        unsigned long long sum = 0ull;
#pragma unroll
        for (int ss = 0; ss < NTEAM; ss++)
            sum = addf2(sum, *(const unsigned long long*)
                        (smf + RED_OFF_F + ss * RED_TEAM_F + ri * REDW + rj));
        F2U c; c.u = sum; return c;
    };

    // prologue: phase-1 tile 0 (tt = s < 64 -> Wh, k0 = 16*s) into stage 0
    {
        int k0 = KT * s;
        cpB(Wh + (size_t)k0 * H_ + jb, H_, 0); CP_COMMIT();
        cpA(g_h[0] + (size_t)b0 * H_ + k0, H_, 0); CP_COMMIT();
    }

    for (int t = 0; t < T_; t++) {
        const float* __restrict__ hb = g_h[cur];

        // ---- FC for previous step's hidden state (row fcrow) ----
        if (t > 0) {
            float sfc[C_];
#pragma unroll
            for (int c = 0; c < C_; c++) sfc[c] = 0.f;
            for (int h = tid; h < H_; h += NTHR) {
                float hv = hb[fcrow * H_ + h];
                const float* w = fcw + h * C_;
#pragma unroll
                for (int c = 0; c < C_; c++) sfc[c] = fmaf(hv, w[c], sfc[c]);
            }
#pragma unroll
            for (int c = 0; c < C_; c++) {
#pragma unroll
                for (int off = 16; off > 0; off >>= 1)
                    sfc[c] += __shfl_xor_sync(0xffffffffu, sfc[c], off);
            }
            if (lane == 0) {
#pragma unroll
                for (int c = 0; c < C_; c++) fcred[s][c] = sfc[c];
            }
            __syncthreads();
            if (tid < C_) {
                float tot = fcb[tid];
#pragma unroll
                for (int w16 = 0; w16 < NTEAM; w16++) tot += fcred[w16][tid];
                out[((size_t)fcrow * T_ + (t - 1)) * C_ + tid] = tot;
            }
        }

        // ================= phase 1: Z = h@Wh + x@Wx + b =================
#pragma unroll
        for (int i = 0; i < 16; i++) acc[i] = 0ull;
#pragma unroll 1
        for (int it = 0; it < 5; it++) {
            if (it < 4) {
                int tt = s + NTEAM * (it + 1);
                if (tt < 64) {
                    int k0 = tt * KT;
                    cpA(hb + (size_t)b0 * H_ + k0, H_, (it + 1) & 1);
                    cpB(Wh + (size_t)k0 * H_ + jb, H_, (it + 1) & 1);
                } else {
                    int k0 = (tt - 64) * KT;
                    cpA(X + ((size_t)b0 * T_ + t) * I_ + k0, (size_t)T_ * I_, (it + 1) & 1);
                    cpB(Wx + (size_t)k0 * H_ + jb, H_, (it + 1) & 1);
                }
                CP_COMMIT();
                CP_WAIT(1);
            } else {
                CP_WAIT(0);
            }
            compute(it & 1);
        }
        // prefetch phase-2 B tile 0 (WhT, barrier-independent) into stage 1
        cpB(g_WhT + (size_t)(KT * s) * H_ + jb, H_, 1); CP_COMMIT();

        write_red();
        __syncthreads();
        {   // epilogue: sum teams + bias -> z; v = a*h - relu(z)
            F2U c = reduce_pair();
            int gi = (b0 + ri) * H_ + jb + rj;
            float2 bz = *(const float2*)(bias + jb + rj);
            float z0 = c.f.x + bz.x, z1 = c.f.y + bz.y;
            float2 h2 = *(const float2*)(hb + gi);
            *(float2*)(g_z + gi) = make_float2(z0, z1);
            *(float2*)(g_v + gi) =
                make_float2(fmaf(a, h2.x, -fmaxf(z0, 0.f)),
                            fmaf(a, h2.y, -fmaxf(z1, 0.f)));
        }
        group_sync(grp);

        // ============ phase 2: G = v @ Wh^T ============
#pragma unroll
        for (int i = 0; i < 16; i++) acc[i] = 0ull;
        cpA(g_v + (size_t)b0 * H_ + KT * s, H_, 1); CP_COMMIT();
#pragma unroll 1
        for (int it = 0; it < 4; it++) {
            if (it < 3) {
                int k0 = (s + NTEAM * (it + 1)) * KT;
                cpA(g_v + (size_t)b0 * H_ + k0, H_, it & 1);
                cpB(g_WhT + (size_t)k0 * H_ + jb, H_, it & 1);
                CP_COMMIT();
                CP_WAIT(1);
            } else {
                CP_WAIT(0);
            }
            compute((it + 1) & 1);
        }
        // prefetch next step's phase-1 B tile 0 (Wh, t-independent) into stage 0
        if (t < T_ - 1) { cpB(Wh + (size_t)(KT * s) * H_ + jb, H_, 0); CP_COMMIT(); }

        write_red();
        __syncthreads();
        {   // epilogue: h update
            float* __restrict__ hn = g_h[cur ^ 1];
            F2U c = reduce_pair();
            int gi = (b0 + ri) * H_ + jb + rj;
            float2 z2 = *(const float2*)(g_z + gi);
            float2 h2 = *(const float2*)(hb + gi);
            float2 v2 = *(const float2*)(g_v + gi);
            float gr0 = a * v2.x - (z2.x > 0.f ? c.f.x : 0.f);
            float gr1 = a * v2.y - (z2.y > 0.f ? c.f.y : 0.f);
            *(float2*)(hn + gi) =
                make_float2(fmaf(-LRC, gr0, h2.x), fmaf(-LRC, gr1, h2.y));
        }
        group_sync(grp);
        cur ^= 1;
        if (t < T_ - 1) {   // phase-1 A tile 0 for next step (new h)
            cpA(g_h[cur] + (size_t)b0 * H_ + KT * s, H_, 0); CP_COMMIT();
        }
    }

    // ---- final FC (t = T-1) + group-local h_final tail ----
    {
        const float* __restrict__ hb = g_h[cur];
        float sfc[C_];
#pragma unroll
        for (int c = 0; c < C_; c++) sfc[c] = 0.f;
        for (int h = tid; h < H_; h += NTHR) {
            float hv = hb[fcrow * H_ + h];
            const float* w = fcw + h * C_;
#pragma unroll
            for (int c = 0; c < C_; c++) sfc[c] = fmaf(hv, w[c], sfc[c]);
        }
#pragma unroll
        for (int c = 0; c < C_; c++) {
#pragma unroll
            for (int off = 16; off > 0; off >>= 1)
                sfc[c] += __shfl_xor_sync(0xffffffffu, sfc[c], off);
        }
        if (lane == 0) {
#pragma unroll
            for (int c = 0; c < C_; c++) fcred[s][c] = sfc[c];
        }
        __syncthreads();
        if (tid < C_) {
            float tot = fcb[tid];
#pragma unroll
            for (int w16 = 0; w16 < NTEAM; w16++) tot += fcred[w16][tid];
            out[((size_t)fcrow * T_ + (T_ - 1)) * C_ + tid] = tot;
        }
        if (write_hf) {
            // RACE FIX vs R13: copy ONLY this group's 32 rows of h_final.
            // Those rows are ordered by this group's final group_sync; other
            // groups' rows are copied by their own CTAs.
            const int cb = bx >> 2;  // 0..31 within group
            for (int idx = cb * NTHR + tid; idx < 32 * H_; idx += 32 * NTHR)
                out[(size_t)B_ * T_ * C_ + (size_t)b0 * H_ + idx] =
                    hb[(size_t)b0 * H_ + idx];
        }
    }
}

extern "C" void kernel_launch(void* const* d_in, const int* in_sizes, int n_in,
                              void* d_out, int out_size) {
    const float *X = 0, *hid = 0, *al = 0, *bi = 0, *Wh = 0, *Wx = 0, *fw = 0, *fb = 0;
    for (int i = 0; i < n_in; i++) {
        const float* p = (const float*)d_in[i];
        switch (in_sizes[i]) {
            case B_ * T_ * I_: X   = p; break;
            case B_ * H_:      hid = p; break;
            case 1:            al  = p; break;
            case H_:           bi  = p; break;
            case H_ * H_:      Wh  = p; break;
            case I_ * H_:      Wx  = p; break;
            case H_ * C_:      fw  = p; break;
            case C_:           fb  = p; break;
            default: break;
        }
    }
    cudaFuncSetAttribute(ode_kernel, cudaFuncAttributeMaxDynamicSharedMemorySize,
                         DYN_SMEM);
    int write_hf = (out_size >= B_ * T_ * C_ + B_ * H_) ? 1 : 0;
    ode_kernel<<<NCTA, NTHR, DYN_SMEM>>>(X, hid, al, bi, Wh, Wx, fw, fb,
                                         (float*)d_out, write_hf);
}